// round 4
// baseline (speedup 1.0000x reference)
#include <cuda_runtime.h>
#include <cstdint>

#define BATCH 1024
#define SEQL  200
#define DIM   128

// Scratch (allocation-free rule: __device__ globals)
__device__ float g_buf[BATCH * DIM];
__device__ float ag_buf[BATCH * DIM];

// Packed fp32x2 FMA (Blackwell FFMA2 — only reachable via PTX fma.rn.f32x2)
__device__ __forceinline__ void ffma2(unsigned long long& d,
                                      unsigned long long a,
                                      unsigned long long b) {
    asm("fma.rn.f32x2 %0, %1, %2, %0;" : "+l"(d) : "l"(a), "l"(b));
}
__device__ __forceinline__ float2 unpack2(unsigned long long v) {
    float2 f;
    asm("mov.b64 {%0, %1}, %2;" : "=f"(f.x), "=f"(f.y) : "l"(v));
    return f;
}

// ---------------------------------------------------------------------------
// Kernel 1: g[b] = sum_l item_embedding[items[b,l]]
// 256 threads: warp w handles rows {w, w+8, ..., w+192} (25 rows), each lane
// loads float4 (cols lane*4..lane*4+3). 5 independent float4 chains -> high
// MLP (5 x 128B outstanding per thread). Cross-warp smem tree reduction.
// ---------------------------------------------------------------------------
__global__ void __launch_bounds__(256) gather_sum_kernel(
    const float* __restrict__ emb,
    const void* __restrict__ items_raw)
{
    const int b    = blockIdx.x;
    const int t    = threadIdx.x;
    const int w    = t >> 5;
    const int lane = t & 31;

    __shared__ int sidx[SEQL];
    __shared__ int mode64;
    __shared__ float4 spart[8][32];

    if (t == 0) {
        // int64 storage => odd int32 words of first 16 elements are all zero
        const int* p = (const int*)items_raw;
        int ok = 1;
        #pragma unroll
        for (int i = 0; i < 16; i++) ok &= (p[2 * i + 1] == 0);
        mode64 = ok;
    }
    __syncthreads();

    if (t < SEQL) {
        if (mode64) sidx[t] = (int)((const long long*)items_raw)[(long long)b * SEQL + t];
        else        sidx[t] = ((const int*)items_raw)[b * SEQL + t];
    }
    __syncthreads();

    float4 acc[5];
    #pragma unroll
    for (int j = 0; j < 5; j++) acc[j] = make_float4(0.f, 0.f, 0.f, 0.f);

    // 25 rows per warp: 5 outer iters x 5 independent chains
    #pragma unroll
    for (int s = 0; s < 5; s++) {
        #pragma unroll
        for (int j = 0; j < 5; j++) {
            const int l = w + 8 * (s * 5 + j);
            const float4 v = *(const float4*)&emb[(size_t)sidx[l] * DIM + lane * 4];
            acc[j].x += v.x; acc[j].y += v.y; acc[j].z += v.z; acc[j].w += v.w;
        }
    }
    float4 s4;
    s4.x = ((acc[0].x + acc[1].x) + (acc[2].x + acc[3].x)) + acc[4].x;
    s4.y = ((acc[0].y + acc[1].y) + (acc[2].y + acc[3].y)) + acc[4].y;
    s4.z = ((acc[0].z + acc[1].z) + (acc[2].z + acc[3].z)) + acc[4].z;
    s4.w = ((acc[0].w + acc[1].w) + (acc[2].w + acc[3].w)) + acc[4].w;

    spart[w][lane] = s4;
    __syncthreads();
    if (w < 4) {
        float4 a = spart[w][lane], c = spart[w + 4][lane];
        a.x += c.x; a.y += c.y; a.z += c.z; a.w += c.w;
        spart[w][lane] = a;
    }
    __syncthreads();
    if (w < 2) {
        float4 a = spart[w][lane], c = spart[w + 2][lane];
        a.x += c.x; a.y += c.y; a.z += c.z; a.w += c.w;
        spart[w][lane] = a;
    }
    __syncthreads();
    if (w == 0) {
        float4 a = spart[0][lane], c = spart[1][lane];
        a.x += c.x; a.y += c.y; a.z += c.z; a.w += c.w;
        *(float4*)&g_buf[b * DIM + lane * 4] = a;
    }
}

// ---------------------------------------------------------------------------
// Kernel 2: Y[1024,128] = Am[1024,1024] @ X[1024,128]  (+fused selu/norm)
//
// grid = 128 blocks (BM=8 rows), block = 512 threads (16 warps = 4/SMSP).
// Thread (r = t>>6, p = t&63) owns output (row bm+r, cols 2p..2p+1) with ONE
// packed f32x2 accumulator spanning the full K=1024 (warps share the staged
// chunk; no cross-warp reduction).
//
// Inner loop = 2 LDS.128 + 2 FFMA2 per 2 k-steps: issue rate == FFMA2 pipe
// floor; 4 warps/SMSP hide LDS/LDG/sync latency.
//  sG[kk2][p] : double2 = {(x[2kk2,2p],x[2kk2,2p+1]), (x[2kk2+1,2p],...)}
//               -> consecutive p = contiguous 16B = conflict-free LDS.128
//  sA[r][kk2] : double2 = {{a,a},{a',a'}} dup pairs -> warp-uniform broadcast
// ---------------------------------------------------------------------------
template <bool EPI>
__global__ void __launch_bounds__(512) gemm_1024x128_kernel(
    const float* __restrict__ Am,
    const float* __restrict__ X,
    float* __restrict__ Y)
{
    const int t  = threadIdx.x;
    const int bm = blockIdx.x * 8;
    const int r  = t >> 6;        // 0..7 output row
    const int p  = t & 63;        // 0..63 col pair

    __shared__ __align__(16) double2 sG[2][16][64];  // 32 KB
    __shared__ __align__(16) double2 sA[2][8][16];   //  4 KB
    __shared__ float wsum[8][2];

    unsigned long long acc = 0ull;

    // X loader: u in {t, t+512}; row k = u>>5 (0..31), c4 = u&31 (float4 col)
    // A loader: t<256: row = t>>5, k = t&31
    float4 xv0, xv1;
    float  av;

    const int xk0 = t >> 5;          // 0..15
    const int xc4 = t & 31;
    const int xk1 = (t + 512) >> 5;  // 16..31
    const int ark = t >> 5;          // A row (t<256)
    const int akk = t & 31;

    // ---- prologue: load + stage chunk 0 ----
    {
        xv0 = *(const float4*)&X[xk0 * DIM + xc4 * 4];
        xv1 = *(const float4*)&X[xk1 * DIM + xc4 * 4];
        if (t < 256) av = Am[(bm + ark) * 1024 + akk];
    }
    {
        ((float2*)&sG[0][xk0 >> 1][2 * xc4])[xk0 & 1]     = make_float2(xv0.x, xv0.y);
        ((float2*)&sG[0][xk0 >> 1][2 * xc4 + 1])[xk0 & 1] = make_float2(xv0.z, xv0.w);
        ((float2*)&sG[0][xk1 >> 1][2 * xc4])[xk1 & 1]     = make_float2(xv1.x, xv1.y);
        ((float2*)&sG[0][xk1 >> 1][2 * xc4 + 1])[xk1 & 1] = make_float2(xv1.z, xv1.w);
        if (t < 256)
            ((float2*)&sA[0][ark][akk >> 1])[akk & 1] = make_float2(av, av);
    }
    __syncthreads();

    // ---- main loop: 32 chunks of K=32, double buffered ----
    #pragma unroll 1
    for (int c = 0; c < 32; c++) {
        const int cur = c & 1;

        if (c < 31) {
            const int k0 = (c + 1) * 32;
            xv0 = *(const float4*)&X[(k0 + xk0) * DIM + xc4 * 4];
            xv1 = *(const float4*)&X[(k0 + xk1) * DIM + xc4 * 4];
            if (t < 256) av = Am[(bm + ark) * 1024 + k0 + akk];
        }

        #pragma unroll
        for (int kk = 0; kk < 16; kk++) {
            const double2 g2 = sG[cur][kk][p];
            const double2 a2 = sA[cur][r][kk];
            ffma2(acc, __double_as_longlong(a2.x), __double_as_longlong(g2.x));
            ffma2(acc, __double_as_longlong(a2.y), __double_as_longlong(g2.y));
        }

        if (c < 31) {
            const int nxt = cur ^ 1;
            ((float2*)&sG[nxt][xk0 >> 1][2 * xc4])[xk0 & 1]     = make_float2(xv0.x, xv0.y);
            ((float2*)&sG[nxt][xk0 >> 1][2 * xc4 + 1])[xk0 & 1] = make_float2(xv0.z, xv0.w);
            ((float2*)&sG[nxt][xk1 >> 1][2 * xc4])[xk1 & 1]     = make_float2(xv1.x, xv1.y);
            ((float2*)&sG[nxt][xk1 >> 1][2 * xc4 + 1])[xk1 & 1] = make_float2(xv1.z, xv1.w);
            if (t < 256)
                ((float2*)&sA[nxt][ark][akk >> 1])[akk & 1] = make_float2(av, av);
        }
        __syncthreads();
    }

    const float2 v = unpack2(acc);

    if (!EPI) {
        *(float2*)&Y[(bm + r) * DIM + 2 * p] = v;
        return;
    }

    // ---- fused epilogue: selu + row L2-normalize ----
    const float SELU_SCALE = 1.0507009873554804934f;
    const float SELU_ALPHA = 1.6732632423543772848f;

    float2 sv;
    sv.x = (v.x > 0.f) ? SELU_SCALE * v.x : SELU_SCALE * SELU_ALPHA * (expf(v.x) - 1.f);
    sv.y = (v.y > 0.f) ? SELU_SCALE * v.y : SELU_SCALE * SELU_ALPHA * (expf(v.y) - 1.f);

    float sq = sv.x * sv.x + sv.y * sv.y;
    #pragma unroll
    for (int o = 16; o; o >>= 1) sq += __shfl_xor_sync(0xFFFFFFFFu, sq, o);
    if ((t & 31) == 0) wsum[r][p >> 5] = sq;   // two warps per row
    __syncthreads();

    const float inv = rsqrtf(wsum[r][0] + wsum[r][1]);
    *(float2*)&Y[(bm + r) * DIM + 2 * p] = make_float2(sv.x * inv, sv.y * inv);
}

// ---------------------------------------------------------------------------
// Launch: gather -> ag = A@g -> out = norm(selu(D@ag))
// (attention/entmax path is analytically identity on g: scores constant
//  along L, entmax of a constant is uniform, sum(p)*g = g)
// ---------------------------------------------------------------------------
extern "C" void kernel_launch(void* const* d_in, const int* in_sizes, int n_in,
                              void* d_out, int out_size)
{
    const float* emb   = (const float*)d_in[0];  // [500000, 128]
    const void*  items = d_in[1];                // [1024, 200] int64/int32
    const float* Amat  = (const float*)d_in[2];  // [1024, 1024]
    const float* Dmat  = (const float*)d_in[3];  // [1024, 1024]
    float* out = (float*)d_out;                  // [1024, 128]

    float* g;  cudaGetSymbolAddress((void**)&g,  g_buf);
    float* ag; cudaGetSymbolAddress((void**)&ag, ag_buf);

    gather_sum_kernel<<<BATCH, 256>>>(emb, items);

    gemm_1024x128_kernel<false><<<BATCH / 8, 512>>>(Amat, g, ag);   // ag = A@g
    gemm_1024x128_kernel<true ><<<BATCH / 8, 512>>>(Dmat, ag, out); // out = norm(selu(D@ag))
}

// round 5
// speedup vs baseline: 1.5113x; 1.5113x over previous
#include <cuda_runtime.h>
#include <cstdint>

#define BATCH 1024
#define SEQL  200
#define DIM   128

// Scratch (allocation-free rule: __device__ globals)
__device__ float g_buf[BATCH * DIM];
__device__ float ag_buf[BATCH * DIM];

// Packed fp32x2 FMA (Blackwell FFMA2 — only reachable via PTX fma.rn.f32x2)
__device__ __forceinline__ void ffma2(unsigned long long& d,
                                      unsigned long long a,
                                      unsigned long long b) {
    asm("fma.rn.f32x2 %0, %1, %2, %0;" : "+l"(d) : "l"(a), "l"(b));
}
__device__ __forceinline__ float2 unpack2(unsigned long long v) {
    float2 f;
    asm("mov.b64 {%0, %1}, %2;" : "=f"(f.x), "=f"(f.y) : "l"(v));
    return f;
}
__device__ __forceinline__ unsigned long long dup2(float g) {
    unsigned long long r;
    asm("mov.b64 %0, {%1, %1};" : "=l"(r) : "f"(g));
    return r;
}

// ---------------------------------------------------------------------------
// Kernel 1: g[b] = sum_l item_embedding[items[b,l]]
// 256 threads: warp w handles rows {w + 8i}, i=0..24, lane = float4 column.
// Ping-pong batches of 5 float4 loads -> ~10 loads in flight per thread.
// ---------------------------------------------------------------------------
__global__ void __launch_bounds__(256) gather_sum_kernel(
    const float* __restrict__ emb,
    const void* __restrict__ items_raw)
{
    const int b    = blockIdx.x;
    const int t    = threadIdx.x;
    const int w    = t >> 5;
    const int lane = t & 31;

    __shared__ int sidx[SEQL];
    __shared__ int mode64;
    __shared__ float4 spart[8][32];

    if (t == 0) {
        // int64 storage => odd int32 words of first 16 elements are all zero
        const int* p = (const int*)items_raw;
        int ok = 1;
        #pragma unroll
        for (int i = 0; i < 16; i++) ok &= (p[2 * i + 1] == 0);
        mode64 = ok;
    }
    __syncthreads();

    if (t < SEQL) {
        if (mode64) sidx[t] = (int)((const long long*)items_raw)[(long long)b * SEQL + t];
        else        sidx[t] = ((const int*)items_raw)[b * SEQL + t];
    }
    __syncthreads();

    float4 acc[5], v[5];
    #pragma unroll
    for (int j = 0; j < 5; j++) acc[j] = make_float4(0.f, 0.f, 0.f, 0.f);

    #pragma unroll
    for (int j = 0; j < 5; j++)
        v[j] = *(const float4*)&emb[(size_t)sidx[w + 8 * j] * DIM + lane * 4];

    #pragma unroll
    for (int s = 0; s < 5; s++) {
        float4 nv[5];
        if (s < 4) {
            #pragma unroll
            for (int j = 0; j < 5; j++)
                nv[j] = *(const float4*)&emb[(size_t)sidx[w + 8 * (5 * (s + 1) + j)] * DIM + lane * 4];
        }
        #pragma unroll
        for (int j = 0; j < 5; j++) {
            acc[j].x += v[j].x; acc[j].y += v[j].y;
            acc[j].z += v[j].z; acc[j].w += v[j].w;
        }
        if (s < 4) {
            #pragma unroll
            for (int j = 0; j < 5; j++) v[j] = nv[j];
        }
    }

    float4 s4;
    s4.x = ((acc[0].x + acc[1].x) + (acc[2].x + acc[3].x)) + acc[4].x;
    s4.y = ((acc[0].y + acc[1].y) + (acc[2].y + acc[3].y)) + acc[4].y;
    s4.z = ((acc[0].z + acc[1].z) + (acc[2].z + acc[3].z)) + acc[4].z;
    s4.w = ((acc[0].w + acc[1].w) + (acc[2].w + acc[3].w)) + acc[4].w;

    spart[w][lane] = s4;
    __syncthreads();
    if (w < 4) {
        float4 a = spart[w][lane], c = spart[w + 4][lane];
        a.x += c.x; a.y += c.y; a.z += c.z; a.w += c.w;
        spart[w][lane] = a;
    }
    __syncthreads();
    if (w < 2) {
        float4 a = spart[w][lane], c = spart[w + 2][lane];
        a.x += c.x; a.y += c.y; a.z += c.z; a.w += c.w;
        spart[w][lane] = a;
    }
    __syncthreads();
    if (w == 0) {
        float4 a = spart[0][lane], c = spart[1][lane];
        a.x += c.x; a.y += c.y; a.z += c.z; a.w += c.w;
        *(float4*)&g_buf[b * DIM + lane * 4] = a;
    }
}

// ---------------------------------------------------------------------------
// Kernel 2: Y[1024,128] = Am[1024,1024] @ X[1024,128]  (+fused selu/norm)
//
// grid = 128 blocks (BM=8 rows), block = 512 threads (16 warps, 4/SMSP).
// Thread (c = t&127, h = t>>7): column c, K-quarter h. Each thread keeps
// ALL 8 output rows as 4 packed row-pair f32x2 accumulators:
//   acc[j] = (out[2j][c], out[2j+1][c]) partial over k in h's quarter.
// A staged TRANSPOSED: sAT[w][k][r] -> {a_r,a_{r+1}} is a natural 8B pair,
// consumed by 2 broadcast LDS.128 per k. g = one LDS.32 + mov.b64 dup.
// Per k: 8 instr (1 LDS.32 + 1 mov + 2 LDS.128 + 4 FFMA2) = FFMA2-rt window.
// Double-buffered 8-k chunks; cross-h smem reduction at the end.
// ---------------------------------------------------------------------------
template <bool EPI>
__global__ void __launch_bounds__(512) gemm_1024x128_kernel(
    const float* __restrict__ Am,
    const float* __restrict__ X,
    float* __restrict__ Y)
{
    const int t  = threadIdx.x;
    const int bm = blockIdx.x * 8;
    const int c  = t & 127;     // column
    const int h  = t >> 7;      // K quarter 0..3

    __shared__ __align__(16) float sX [2][4][8][128];  // 32 KB [buf][w][k][c]
    __shared__ __align__(16) float sAT[2][4][8][8];    //  2 KB [buf][w][k][r]
    __shared__ __align__(16) float red[3][128][8];     // 12 KB cross-h partials
    __shared__ float wpart[4][8];

    unsigned long long acc[4] = {0ull, 0ull, 0ull, 0ull};

    // X loader: 2 float4 per thread per chunk. u in [0,1024):
    //   w = u>>8, k = (u>>5)&7, c4 = u&31
    // A loader: t<256: w = t>>6, k = (t>>3)&7, r = t&7
    float4 xv0, xv1;
    float  av;

    const int u0 = t, u1 = t + 512;
    const int xw0 = u0 >> 8, xk0 = (u0 >> 5) & 7, xc0 = u0 & 31;
    const int xw1 = u1 >> 8, xk1 = (u1 >> 5) & 7, xc1 = u1 & 31;
    const int aw = t >> 6, ak = (t >> 3) & 7, ar = t & 7;

    // ---- prologue: load + stage chunk 0 ----
    xv0 = *(const float4*)&X[(xw0 * 256 + xk0) * DIM + xc0 * 4];
    xv1 = *(const float4*)&X[(xw1 * 256 + xk1) * DIM + xc1 * 4];
    if (t < 256) av = Am[(bm + ar) * 1024 + aw * 256 + ak];

    *(float4*)&sX[0][xw0][xk0][xc0 * 4] = xv0;
    *(float4*)&sX[0][xw1][xk1][xc1 * 4] = xv1;
    if (t < 256) sAT[0][aw][ak][ar] = av;
    __syncthreads();

    // ---- main loop: 32 chunks of 8 k per window, double buffered ----
    #pragma unroll 1
    for (int ch = 0; ch < 32; ch++) {
        const int cur = ch & 1;

        if (ch < 31) {
            const int ko = (ch + 1) * 8;
            xv0 = *(const float4*)&X[(xw0 * 256 + ko + xk0) * DIM + xc0 * 4];
            xv1 = *(const float4*)&X[(xw1 * 256 + ko + xk1) * DIM + xc1 * 4];
            if (t < 256) av = Am[(bm + ar) * 1024 + aw * 256 + ko + ak];
        }

        #pragma unroll
        for (int kk = 0; kk < 8; kk++) {
            const float g = sX[cur][h][kk][c];
            const unsigned long long gd = dup2(g);
            const double2 a03 = *(const double2*)&sAT[cur][h][kk][0];
            const double2 a47 = *(const double2*)&sAT[cur][h][kk][4];
            ffma2(acc[0], __double_as_longlong(a03.x), gd);
            ffma2(acc[1], __double_as_longlong(a03.y), gd);
            ffma2(acc[2], __double_as_longlong(a47.x), gd);
            ffma2(acc[3], __double_as_longlong(a47.y), gd);
        }

        if (ch < 31) {
            const int nxt = cur ^ 1;
            *(float4*)&sX[nxt][xw0][xk0][xc0 * 4] = xv0;
            *(float4*)&sX[nxt][xw1][xk1][xc1 * 4] = xv1;
            if (t < 256) sAT[nxt][aw][ak][ar] = av;
        }
        __syncthreads();
    }

    // ---- cross-h reduction ----
    float s[8];
    #pragma unroll
    for (int j = 0; j < 4; j++) {
        const float2 f = unpack2(acc[j]);
        s[2 * j] = f.x; s[2 * j + 1] = f.y;
    }
    if (h > 0) {
        #pragma unroll
        for (int j = 0; j < 8; j++) red[h - 1][c][j] = s[j];
    }
    __syncthreads();

    float sv[8];
    if (h == 0) {
        #pragma unroll
        for (int hh = 0; hh < 3; hh++)
            #pragma unroll
            for (int j = 0; j < 8; j++) s[j] += red[hh][c][j];

        if (!EPI) {
            #pragma unroll
            for (int j = 0; j < 8; j++) Y[(bm + j) * DIM + c] = s[j];
        } else {
            const float SELU_SCALE = 1.0507009873554804934f;
            const float SELU_ALPHA = 1.6732632423543772848f;
            float sq[8];
            #pragma unroll
            for (int j = 0; j < 8; j++) {
                sv[j] = (s[j] > 0.f) ? SELU_SCALE * s[j]
                                     : SELU_SCALE * SELU_ALPHA * (expf(s[j]) - 1.f);
                sq[j] = sv[j] * sv[j];
            }
            #pragma unroll
            for (int j = 0; j < 8; j++)
                #pragma unroll
                for (int o = 16; o; o >>= 1)
                    sq[j] += __shfl_xor_sync(0xFFFFFFFFu, sq[j], o);
            if ((c & 31) == 0) {
                #pragma unroll
                for (int j = 0; j < 8; j++) wpart[c >> 5][j] = sq[j];
            }
        }
    }

    if (EPI) {
        __syncthreads();
        if (h == 0) {
            #pragma unroll
            for (int j = 0; j < 8; j++) {
                const float inv = rsqrtf(wpart[0][j] + wpart[1][j] + wpart[2][j] + wpart[3][j]);
                Y[(bm + j) * DIM + c] = sv[j] * inv;
            }
        }
    }
}

// ---------------------------------------------------------------------------
// Launch: gather -> ag = A@g -> out = norm(selu(D@ag))
// (attention/entmax path is analytically identity on g: scores constant
//  along L, entmax of a constant is uniform, sum(p)*g = g)
// ---------------------------------------------------------------------------
extern "C" void kernel_launch(void* const* d_in, const int* in_sizes, int n_in,
                              void* d_out, int out_size)
{
    const float* emb   = (const float*)d_in[0];  // [500000, 128]
    const void*  items = d_in[1];                // [1024, 200] int64/int32
    const float* Amat  = (const float*)d_in[2];  // [1024, 1024]
    const float* Dmat  = (const float*)d_in[3];  // [1024, 1024]
    float* out = (float*)d_out;                  // [1024, 128]

    float* g;  cudaGetSymbolAddress((void**)&g,  g_buf);
    float* ag; cudaGetSymbolAddress((void**)&ag, ag_buf);

    gather_sum_kernel<<<BATCH, 256>>>(emb, items);

    gemm_1024x128_kernel<false><<<BATCH / 8, 512>>>(Amat, g, ag);   // ag = A@g
    gemm_1024x128_kernel<true ><<<BATCH / 8, 512>>>(Dmat, ag, out); // out = norm(selu(D@ag))
}

// round 6
// speedup vs baseline: 1.5540x; 1.0283x over previous
#include <cuda_runtime.h>
#include <cstdint>

#define BATCH 1024
#define SEQL  200
#define DIM   128

// Scratch (allocation-free rule: __device__ globals)
__device__ float g_buf[BATCH * DIM];
__device__ float ag_buf[BATCH * DIM];

// ---------------------------------------------------------------------------
// Kernel 1: g[b] = sum_l item_embedding[items[b,l]]
// 256 threads: warp w handles rows {w + 8i}, i=0..24, lane = float4 column.
// Ping-pong batches of 5 float4 loads -> ~10 loads in flight per thread.
// ---------------------------------------------------------------------------
__global__ void __launch_bounds__(256) gather_sum_kernel(
    const float* __restrict__ emb,
    const void* __restrict__ items_raw)
{
    const int b    = blockIdx.x;
    const int t    = threadIdx.x;
    const int w    = t >> 5;
    const int lane = t & 31;

    __shared__ int sidx[SEQL];
    __shared__ int mode64;
    __shared__ float4 spart[8][32];

    if (t == 0) {
        // int64 storage => odd int32 words of first 16 elements are all zero
        const int* p = (const int*)items_raw;
        int ok = 1;
        #pragma unroll
        for (int i = 0; i < 16; i++) ok &= (p[2 * i + 1] == 0);
        mode64 = ok;
    }
    __syncthreads();

    if (t < SEQL) {
        if (mode64) sidx[t] = (int)((const long long*)items_raw)[(long long)b * SEQL + t];
        else        sidx[t] = ((const int*)items_raw)[b * SEQL + t];
    }
    __syncthreads();

    float4 acc[5], v[5];
    #pragma unroll
    for (int j = 0; j < 5; j++) acc[j] = make_float4(0.f, 0.f, 0.f, 0.f);

    #pragma unroll
    for (int j = 0; j < 5; j++)
        v[j] = *(const float4*)&emb[(size_t)sidx[w + 8 * j] * DIM + lane * 4];

    #pragma unroll
    for (int s = 0; s < 5; s++) {
        float4 nv[5];
        if (s < 4) {
            #pragma unroll
            for (int j = 0; j < 5; j++)
                nv[j] = *(const float4*)&emb[(size_t)sidx[w + 8 * (5 * (s + 1) + j)] * DIM + lane * 4];
        }
        #pragma unroll
        for (int j = 0; j < 5; j++) {
            acc[j].x += v[j].x; acc[j].y += v[j].y;
            acc[j].z += v[j].z; acc[j].w += v[j].w;
        }
        if (s < 4) {
            #pragma unroll
            for (int j = 0; j < 5; j++) v[j] = nv[j];
        }
    }

    float4 s4;
    s4.x = ((acc[0].x + acc[1].x) + (acc[2].x + acc[3].x)) + acc[4].x;
    s4.y = ((acc[0].y + acc[1].y) + (acc[2].y + acc[3].y)) + acc[4].y;
    s4.z = ((acc[0].z + acc[1].z) + (acc[2].z + acc[3].z)) + acc[4].z;
    s4.w = ((acc[0].w + acc[1].w) + (acc[2].w + acc[3].w)) + acc[4].w;

    spart[w][lane] = s4;
    __syncthreads();
    if (w < 4) {
        float4 a = spart[w][lane], c = spart[w + 4][lane];
        a.x += c.x; a.y += c.y; a.z += c.z; a.w += c.w;
        spart[w][lane] = a;
    }
    __syncthreads();
    if (w < 2) {
        float4 a = spart[w][lane], c = spart[w + 2][lane];
        a.x += c.x; a.y += c.y; a.z += c.z; a.w += c.w;
        spart[w][lane] = a;
    }
    __syncthreads();
    if (w == 0) {
        float4 a = spart[0][lane], c = spart[1][lane];
        a.x += c.x; a.y += c.y; a.z += c.z; a.w += c.w;
        *(float4*)&g_buf[b * DIM + lane * 4] = a;
    }
}

// ---------------------------------------------------------------------------
// Kernel 2: Y[1024,128] = Am[1024,1024] @ X[1024,128]  (+fused selu/norm)
//
// grid = 128 blocks (BM=8 rows), block = 512 threads (16 warps, 4/SMSP).
// Thread (c = t&127, h = t>>7): column c, K-quarter h. Each thread keeps
// ALL 8 output rows as scalar fp32 accumulators (M-reuse = 8).
// A staged TRANSPOSED: sAT[w][k][r] -> rows consumed as 2 broadcast LDS.128.
// Per kk: 11 instr (1 LDS.32 + 2 LDS.128 + 8 FFMA): issue 11.6k cyc/SMSP <
// FFMA pipe budget 16.4k cyc -> FFMA-bound. Plain C++ fmaf -> clean SASS
// (no 64-bit asm operand churn). Double-buffered 8-k chunks.
// ---------------------------------------------------------------------------
template <bool EPI>
__global__ void __launch_bounds__(512) gemm_1024x128_kernel(
    const float* __restrict__ Am,
    const float* __restrict__ X,
    float* __restrict__ Y)
{
    const int t  = threadIdx.x;
    const int bm = blockIdx.x * 8;
    const int c  = t & 127;     // column
    const int h  = t >> 7;      // K quarter 0..3

    __shared__ __align__(16) float sX [2][4][8][128];  // 32 KB [buf][w][k][c]
    __shared__ __align__(16) float sAT[2][4][8][8];    //  2 KB [buf][w][k][r]
    __shared__ __align__(16) float red[3][128][8];     // 12 KB cross-h partials
    __shared__ float wpart[4][8];

    float acc[8] = {0.f, 0.f, 0.f, 0.f, 0.f, 0.f, 0.f, 0.f};

    // X loader: 2 float4 per thread per chunk. u in [0,1024):
    //   w = u>>8, k = (u>>5)&7, c4 = u&31
    // A loader: t<256: w = t>>6, k = (t>>3)&7, r = t&7
    float4 xv0, xv1;
    float  av;

    const int u0 = t, u1 = t + 512;
    const int xw0 = u0 >> 8, xk0 = (u0 >> 5) & 7, xc0 = u0 & 31;
    const int xw1 = u1 >> 8, xk1 = (u1 >> 5) & 7, xc1 = u1 & 31;
    const int aw = t >> 6, ak = (t >> 3) & 7, ar = t & 7;

    // ---- prologue: load + stage chunk 0 ----
    xv0 = *(const float4*)&X[(xw0 * 256 + xk0) * DIM + xc0 * 4];
    xv1 = *(const float4*)&X[(xw1 * 256 + xk1) * DIM + xc1 * 4];
    if (t < 256) av = Am[(bm + ar) * 1024 + aw * 256 + ak];

    *(float4*)&sX[0][xw0][xk0][xc0 * 4] = xv0;
    *(float4*)&sX[0][xw1][xk1][xc1 * 4] = xv1;
    if (t < 256) sAT[0][aw][ak][ar] = av;
    __syncthreads();

    // ---- main loop: 32 chunks of 8 k per quarter, double buffered ----
    #pragma unroll 1
    for (int ch = 0; ch < 32; ch++) {
        const int cur = ch & 1;

        if (ch < 31) {
            const int ko = (ch + 1) * 8;
            xv0 = *(const float4*)&X[(xw0 * 256 + ko + xk0) * DIM + xc0 * 4];
            xv1 = *(const float4*)&X[(xw1 * 256 + ko + xk1) * DIM + xc1 * 4];
            if (t < 256) av = Am[(bm + ar) * 1024 + aw * 256 + ko + ak];
        }

        #pragma unroll
        for (int kk = 0; kk < 8; kk++) {
            const float  g   = sX[cur][h][kk][c];
            const float4 a03 = *(const float4*)&sAT[cur][h][kk][0];
            const float4 a47 = *(const float4*)&sAT[cur][h][kk][4];
            acc[0] = fmaf(a03.x, g, acc[0]);
            acc[1] = fmaf(a03.y, g, acc[1]);
            acc[2] = fmaf(a03.z, g, acc[2]);
            acc[3] = fmaf(a03.w, g, acc[3]);
            acc[4] = fmaf(a47.x, g, acc[4]);
            acc[5] = fmaf(a47.y, g, acc[5]);
            acc[6] = fmaf(a47.z, g, acc[6]);
            acc[7] = fmaf(a47.w, g, acc[7]);
        }

        if (ch < 31) {
            const int nxt = cur ^ 1;
            *(float4*)&sX[nxt][xw0][xk0][xc0 * 4] = xv0;
            *(float4*)&sX[nxt][xw1][xk1][xc1 * 4] = xv1;
            if (t < 256) sAT[nxt][aw][ak][ar] = av;
        }
        __syncthreads();
    }

    // ---- cross-h reduction ----
    if (h > 0) {
        #pragma unroll
        for (int j = 0; j < 8; j++) red[h - 1][c][j] = acc[j];
    }
    __syncthreads();

    float sv[8];
    if (h == 0) {
        #pragma unroll
        for (int hh = 0; hh < 3; hh++)
            #pragma unroll
            for (int j = 0; j < 8; j++) acc[j] += red[hh][c][j];

        if (!EPI) {
            #pragma unroll
            for (int j = 0; j < 8; j++) Y[(bm + j) * DIM + c] = acc[j];
        } else {
            const float SELU_SCALE = 1.0507009873554804934f;
            const float SELU_ALPHA = 1.6732632423543772848f;
            float sq[8];
            #pragma unroll
            for (int j = 0; j < 8; j++) {
                sv[j] = (acc[j] > 0.f) ? SELU_SCALE * acc[j]
                                       : SELU_SCALE * SELU_ALPHA * (expf(acc[j]) - 1.f);
                sq[j] = sv[j] * sv[j];
            }
            #pragma unroll
            for (int j = 0; j < 8; j++)
                #pragma unroll
                for (int o = 16; o; o >>= 1)
                    sq[j] += __shfl_xor_sync(0xFFFFFFFFu, sq[j], o);
            if ((c & 31) == 0) {
                #pragma unroll
                for (int j = 0; j < 8; j++) wpart[c >> 5][j] = sq[j];
            }
        }
    }

    if (EPI) {
        __syncthreads();
        if (h == 0) {
            #pragma unroll
            for (int j = 0; j < 8; j++) {
                const float inv = rsqrtf(wpart[0][j] + wpart[1][j] + wpart[2][j] + wpart[3][j]);
                Y[(bm + j) * DIM + c] = sv[j] * inv;
            }
        }
    }
}

// ---------------------------------------------------------------------------
// Launch: gather -> ag = A@g -> out = norm(selu(D@ag))
// (attention/entmax path is analytically identity on g: scores constant
//  along L, entmax of a constant is uniform, sum(p)*g = g)
// ---------------------------------------------------------------------------
extern "C" void kernel_launch(void* const* d_in, const int* in_sizes, int n_in,
                              void* d_out, int out_size)
{
    const float* emb   = (const float*)d_in[0];  // [500000, 128]
    const void*  items = d_in[1];                // [1024, 200] int64/int32
    const float* Amat  = (const float*)d_in[2];  // [1024, 1024]
    const float* Dmat  = (const float*)d_in[3];  // [1024, 1024]
    float* out = (float*)d_out;                  // [1024, 128]

    float* g;  cudaGetSymbolAddress((void**)&g,  g_buf);
    float* ag; cudaGetSymbolAddress((void**)&ag, ag_buf);

    gather_sum_kernel<<<BATCH, 256>>>(emb, items);

    gemm_1024x128_kernel<false><<<BATCH / 8, 512>>>(Amat, g, ag);   // ag = A@g
    gemm_1024x128_kernel<true ><<<BATCH / 8, 512>>>(Dmat, ag, out); // out = norm(selu(D@ag))
}

// round 7
// speedup vs baseline: 1.7750x; 1.1422x over previous
#include <cuda_runtime.h>
#include <cstdint>

#define BATCH 1024
#define SEQL  200
#define DIM   128

// Scratch (allocation-free rule: __device__ globals)
__device__ float g_buf[BATCH * DIM];
__device__ float ag_buf[BATCH * DIM];

// ---------------------------------------------------------------------------
// Kernel 1: g[b] = sum_l item_embedding[items[b,l]]
// 256 threads: warp w handles rows {w + 8i}, i=0..24, lane = float4 column.
// Ping-pong batches of 5 float4 loads -> ~10 loads in flight per thread.
// ---------------------------------------------------------------------------
__global__ void __launch_bounds__(256) gather_sum_kernel(
    const float* __restrict__ emb,
    const void* __restrict__ items_raw)
{
    const int b    = blockIdx.x;
    const int t    = threadIdx.x;
    const int w    = t >> 5;
    const int lane = t & 31;

    __shared__ int sidx[SEQL];
    __shared__ int mode64;
    __shared__ float4 spart[8][32];

    if (t == 0) {
        // int64 storage => odd int32 words of first 16 elements are all zero
        const int* p = (const int*)items_raw;
        int ok = 1;
        #pragma unroll
        for (int i = 0; i < 16; i++) ok &= (p[2 * i + 1] == 0);
        mode64 = ok;
    }
    __syncthreads();

    if (t < SEQL) {
        if (mode64) sidx[t] = (int)((const long long*)items_raw)[(long long)b * SEQL + t];
        else        sidx[t] = ((const int*)items_raw)[b * SEQL + t];
    }
    __syncthreads();

    float4 acc[5], v[5];
    #pragma unroll
    for (int j = 0; j < 5; j++) acc[j] = make_float4(0.f, 0.f, 0.f, 0.f);

    #pragma unroll
    for (int j = 0; j < 5; j++)
        v[j] = *(const float4*)&emb[(size_t)sidx[w + 8 * j] * DIM + lane * 4];

    #pragma unroll
    for (int s = 0; s < 5; s++) {
        float4 nv[5];
        if (s < 4) {
            #pragma unroll
            for (int j = 0; j < 5; j++)
                nv[j] = *(const float4*)&emb[(size_t)sidx[w + 8 * (5 * (s + 1) + j)] * DIM + lane * 4];
        }
        #pragma unroll
        for (int j = 0; j < 5; j++) {
            acc[j].x += v[j].x; acc[j].y += v[j].y;
            acc[j].z += v[j].z; acc[j].w += v[j].w;
        }
        if (s < 4) {
            #pragma unroll
            for (int j = 0; j < 5; j++) v[j] = nv[j];
        }
    }

    float4 s4;
    s4.x = ((acc[0].x + acc[1].x) + (acc[2].x + acc[3].x)) + acc[4].x;
    s4.y = ((acc[0].y + acc[1].y) + (acc[2].y + acc[3].y)) + acc[4].y;
    s4.z = ((acc[0].z + acc[1].z) + (acc[2].z + acc[3].z)) + acc[4].z;
    s4.w = ((acc[0].w + acc[1].w) + (acc[2].w + acc[3].w)) + acc[4].w;

    spart[w][lane] = s4;
    __syncthreads();
    if (w < 4) {
        float4 a = spart[w][lane], c = spart[w + 4][lane];
        a.x += c.x; a.y += c.y; a.z += c.z; a.w += c.w;
        spart[w][lane] = a;
    }
    __syncthreads();
    if (w < 2) {
        float4 a = spart[w][lane], c = spart[w + 2][lane];
        a.x += c.x; a.y += c.y; a.z += c.z; a.w += c.w;
        spart[w][lane] = a;
    }
    __syncthreads();
    if (w == 0) {
        float4 a = spart[0][lane], c = spart[1][lane];
        a.x += c.x; a.y += c.y; a.z += c.z; a.w += c.w;
        *(float4*)&g_buf[b * DIM + lane * 4] = a;
    }
}

// ---------------------------------------------------------------------------
// Kernel 2: Y[1024,128] = Am[1024,1024] @ X[1024,128]  (+fused selu/norm)
//
// grid = 128 blocks (BM=8 rows), block = 512 threads (16 warps, 4/SMSP).
// Thread (c = t&127, h = t>>7): column c, K-quarter h; 8 scalar row accs.
// A pipeline: 4-buffer smem ring. LDG for chunk ch+3 at chunk ch, STS at
// chunk ch+1 (1-chunk register gap buries DRAM latency), read at ch+3.
// X pipeline: classic double buffer (L2-resident, 1-chunk gap suffices).
// Cross-h reduction array ALIASES the dead sX buffers after the main loop
// (keeps static smem at 37KB).
// ---------------------------------------------------------------------------
template <bool EPI>
__global__ void __launch_bounds__(512) gemm_1024x128_kernel(
    const float* __restrict__ Am,
    const float* __restrict__ X,
    float* __restrict__ Y)
{
    const int t  = threadIdx.x;
    const int bm = blockIdx.x * 8;
    const int c  = t & 127;     // column
    const int h  = t >> 7;      // K quarter 0..3

    __shared__ __align__(16) float sX [2][4][8][128];  // 32 KB [xbuf][q][k][c]
    __shared__ __align__(16) float sAT[4][4][8][8];    //  4 KB [ring][q][k][r]
    __shared__ float wpart[4][8];

    // red[hh][c][j] aliases sX (dead after the main loop): 3*128*8 floats = 12KB
    float* redf = &sX[0][0][0][0];

    float acc[8] = {0.f, 0.f, 0.f, 0.f, 0.f, 0.f, 0.f, 0.f};

    // X loader: 2 float4 per thread per chunk
    const int u0 = t, u1 = t + 512;
    const int xw0 = u0 >> 8, xk0 = (u0 >> 5) & 7, xc0 = u0 & 31;
    const int xw1 = u1 >> 8, xk1 = (u1 >> 5) & 7, xc1 = u1 & 31;
    // A loader (t<256): quarter aw, col-in-chunk ak, row ar
    const int aw = t >> 6, ak = (t >> 3) & 7, ar = t & 7;
    const float* Arow = Am + (bm + ar) * 1024 + aw * 256 + ak;

    float4 xv0, xv1;
    float  a_mid, a_new;

    // ---- prologue ----
    xv0 = *(const float4*)&X[(xw0 * 256 + xk0) * DIM + xc0 * 4];
    xv1 = *(const float4*)&X[(xw1 * 256 + xk1) * DIM + xc1 * 4];
    *(float4*)&sX[0][xw0][xk0][xc0 * 4] = xv0;
    *(float4*)&sX[0][xw1][xk1][xc1 * 4] = xv1;
    if (t < 256) {
        sAT[0][aw][ak][ar] = Arow[0];        // chunk 0
        sAT[1][aw][ak][ar] = Arow[8];        // chunk 1
        a_mid = Arow[16];                    // chunk 2 (STS at ch=0)
    }
    __syncthreads();

    // ---- main loop: 32 chunks of 8 k per quarter ----
    #pragma unroll 1
    for (int ch = 0; ch < 32; ch++) {
        const int curX = ch & 1;

        if (ch < 31) {
            const int ko = (ch + 1) * 8;
            xv0 = *(const float4*)&X[(xw0 * 256 + ko + xk0) * DIM + xc0 * 4];
            xv1 = *(const float4*)&X[(xw1 * 256 + ko + xk1) * DIM + xc1 * 4];
        }
        if (t < 256 && ch + 3 < 32)
            a_new = Arow[(ch + 3) * 8];      // for chunk ch+3, STS'd at ch+1

        const int abuf = ch & 3;
        #pragma unroll
        for (int kk = 0; kk < 8; kk++) {
            const float  g   = sX[curX][h][kk][c];
            const float4 a03 = *(const float4*)&sAT[abuf][h][kk][0];
            const float4 a47 = *(const float4*)&sAT[abuf][h][kk][4];
            acc[0] = fmaf(a03.x, g, acc[0]);
            acc[1] = fmaf(a03.y, g, acc[1]);
            acc[2] = fmaf(a03.z, g, acc[2]);
            acc[3] = fmaf(a03.w, g, acc[3]);
            acc[4] = fmaf(a47.x, g, acc[4]);
            acc[5] = fmaf(a47.y, g, acc[5]);
            acc[6] = fmaf(a47.z, g, acc[6]);
            acc[7] = fmaf(a47.w, g, acc[7]);
        }

        if (ch < 31) {
            const int nxtX = curX ^ 1;
            *(float4*)&sX[nxtX][xw0][xk0][xc0 * 4] = xv0;
            *(float4*)&sX[nxtX][xw1][xk1][xc1 * 4] = xv1;
        }
        if (t < 256 && ch + 2 < 32) {
            sAT[(ch + 2) & 3][aw][ak][ar] = a_mid;   // loaded at ch-1 (or prologue)
            a_mid = a_new;
        }
        __syncthreads();
    }

    // ---- cross-h reduction (red aliases sX; all sX reads are done) ----
    if (h > 0) {
        #pragma unroll
        for (int j = 0; j < 8; j++) redf[((h - 1) * 128 + c) * 8 + j] = acc[j];
    }
    __syncthreads();

    float sv[8];
    if (h == 0) {
        #pragma unroll
        for (int hh = 0; hh < 3; hh++)
            #pragma unroll
            for (int j = 0; j < 8; j++) acc[j] += redf[(hh * 128 + c) * 8 + j];

        if (!EPI) {
            #pragma unroll
            for (int j = 0; j < 8; j++) Y[(bm + j) * DIM + c] = acc[j];
        } else {
            const float SELU_SCALE = 1.0507009873554804934f;
            const float SELU_ALPHA = 1.6732632423543772848f;
            float sq[8];
            #pragma unroll
            for (int j = 0; j < 8; j++) {
                sv[j] = (acc[j] > 0.f) ? SELU_SCALE * acc[j]
                                       : SELU_SCALE * SELU_ALPHA * (expf(acc[j]) - 1.f);
                sq[j] = sv[j] * sv[j];
            }
            #pragma unroll
            for (int j = 0; j < 8; j++)
                #pragma unroll
                for (int o = 16; o; o >>= 1)
                    sq[j] += __shfl_xor_sync(0xFFFFFFFFu, sq[j], o);
            if ((c & 31) == 0) {
                #pragma unroll
                for (int j = 0; j < 8; j++) wpart[c >> 5][j] = sq[j];
            }
        }
    }

    if (EPI) {
        __syncthreads();
        if (h == 0) {
            #pragma unroll
            for (int j = 0; j < 8; j++) {
                const float inv = rsqrtf(wpart[0][j] + wpart[1][j] + wpart[2][j] + wpart[3][j]);
                Y[(bm + j) * DIM + c] = sv[j] * inv;
            }
        }
    }
}

// ---------------------------------------------------------------------------
// Launch: gather -> ag = A@g -> out = norm(selu(D@ag))
// (attention/entmax path is analytically identity on g: scores constant
//  along L, entmax of a constant is uniform, sum(p)*g = g)
// ---------------------------------------------------------------------------
extern "C" void kernel_launch(void* const* d_in, const int* in_sizes, int n_in,
                              void* d_out, int out_size)
{
    const float* emb   = (const float*)d_in[0];  // [500000, 128]
    const void*  items = d_in[1];                // [1024, 200] int64/int32
    const float* Amat  = (const float*)d_in[2];  // [1024, 1024]
    const float* Dmat  = (const float*)d_in[3];  // [1024, 1024]
    float* out = (float*)d_out;                  // [1024, 128]

    float* g;  cudaGetSymbolAddress((void**)&g,  g_buf);
    float* ag; cudaGetSymbolAddress((void**)&ag, ag_buf);

    gather_sum_kernel<<<BATCH, 256>>>(emb, items);

    gemm_1024x128_kernel<false><<<BATCH / 8, 512>>>(Amat, g, ag);   // ag = A@g
    gemm_1024x128_kernel<true ><<<BATCH / 8, 512>>>(Dmat, ag, out); // out = norm(selu(D@ag))
}

// round 8
// speedup vs baseline: 2.3279x; 1.3115x over previous
#include <cuda_runtime.h>
#include <cstdint>

#define BATCH 1024
#define SEQL  200
#define DIM   128

// Scratch (allocation-free rule: __device__ globals)
__device__ float g_buf[BATCH * DIM];
__device__ float ag_buf[BATCH * DIM];

// ---------------------------------------------------------------------------
// Kernel 1: g[b] = sum_l item_embedding[items[b,l]]
// 256 threads: warp w handles rows {w + 8i}, i=0..24, lane = float4 column.
// Ping-pong batches of 5 float4 loads -> ~10 loads in flight per thread.
// ---------------------------------------------------------------------------
__global__ void __launch_bounds__(256) gather_sum_kernel(
    const float* __restrict__ emb,
    const void* __restrict__ items_raw)
{
    const int b    = blockIdx.x;
    const int t    = threadIdx.x;
    const int w    = t >> 5;
    const int lane = t & 31;

    __shared__ int sidx[SEQL];
    __shared__ int mode64;
    __shared__ float4 spart[8][32];

    if (t == 0) {
        // int64 storage => odd int32 words of first 16 elements are all zero
        const int* p = (const int*)items_raw;
        int ok = 1;
        #pragma unroll
        for (int i = 0; i < 16; i++) ok &= (p[2 * i + 1] == 0);
        mode64 = ok;
    }
    __syncthreads();

    if (t < SEQL) {
        if (mode64) sidx[t] = (int)((const long long*)items_raw)[(long long)b * SEQL + t];
        else        sidx[t] = ((const int*)items_raw)[b * SEQL + t];
    }
    __syncthreads();

    float4 acc[5], v[5];
    #pragma unroll
    for (int j = 0; j < 5; j++) acc[j] = make_float4(0.f, 0.f, 0.f, 0.f);

    #pragma unroll
    for (int j = 0; j < 5; j++)
        v[j] = *(const float4*)&emb[(size_t)sidx[w + 8 * j] * DIM + lane * 4];

    #pragma unroll
    for (int s = 0; s < 5; s++) {
        float4 nv[5];
        if (s < 4) {
            #pragma unroll
            for (int j = 0; j < 5; j++)
                nv[j] = *(const float4*)&emb[(size_t)sidx[w + 8 * (5 * (s + 1) + j)] * DIM + lane * 4];
        }
        #pragma unroll
        for (int j = 0; j < 5; j++) {
            acc[j].x += v[j].x; acc[j].y += v[j].y;
            acc[j].z += v[j].z; acc[j].w += v[j].w;
        }
        if (s < 4) {
            #pragma unroll
            for (int j = 0; j < 5; j++) v[j] = nv[j];
        }
    }

    float4 s4;
    s4.x = ((acc[0].x + acc[1].x) + (acc[2].x + acc[3].x)) + acc[4].x;
    s4.y = ((acc[0].y + acc[1].y) + (acc[2].y + acc[3].y)) + acc[4].y;
    s4.z = ((acc[0].z + acc[1].z) + (acc[2].z + acc[3].z)) + acc[4].z;
    s4.w = ((acc[0].w + acc[1].w) + (acc[2].w + acc[3].w)) + acc[4].w;

    spart[w][lane] = s4;
    __syncthreads();
    if (w < 4) {
        float4 a = spart[w][lane], c = spart[w + 4][lane];
        a.x += c.x; a.y += c.y; a.z += c.z; a.w += c.w;
        spart[w][lane] = a;
    }
    __syncthreads();
    if (w < 2) {
        float4 a = spart[w][lane], c = spart[w + 2][lane];
        a.x += c.x; a.y += c.y; a.z += c.z; a.w += c.w;
        spart[w][lane] = a;
    }
    __syncthreads();
    if (w == 0) {
        float4 a = spart[0][lane], c = spart[1][lane];
        a.x += c.x; a.y += c.y; a.z += c.z; a.w += c.w;
        *(float4*)&g_buf[b * DIM + lane * 4] = a;
    }
}

// ---------------------------------------------------------------------------
// Kernel 2: Y[1024,128] = Am[1024,1024] @ X[1024,128]  (+fused selu/norm)
//
// grid = 128 blocks (BM=8 rows), block = 512 threads (16 warps, 4/SMSP).
// Thread (c = t&127, h = t>>7): column c, K-quarter h; 8 scalar row accs.
//
// BARRIER-FREE MAINLOOP:
//  - The full A slice (8 rows x 1024 K = 32 KB) is staged in smem ONCE in
//    the prologue (single __syncthreads). Mainloop reads it via broadcast
//    LDS.128 only -> no producer/consumer sync ever again.
//  - g values live in REGISTERS: each thread streams its own column
//    X[k*128+c] (warp-coalesced 128B lines, L2-resident), ping-pong one
//    8-value chunk ahead. No smem staging for X at all.
//  - Per kk: 2 broadcast LDS.128 + 8 FFMA = 10 instrs; 4 fully independent
//    warps/SMSP -> FFMA-pipe-bound (16.4k cyc/SMSP per GEMM).
//  - Cross-quarter reduction aliases the then-dead sA (2 end barriers).
// ---------------------------------------------------------------------------
template <bool EPI>
__global__ void __launch_bounds__(512) gemm_1024x128_kernel(
    const float* __restrict__ Am,
    const float* __restrict__ X,
    float* __restrict__ Y)
{
    const int t  = threadIdx.x;
    const int bm = blockIdx.x * 8;
    const int c  = t & 127;     // column
    const int h  = t >> 7;      // K quarter 0..3

    __shared__ __align__(16) float sA[1024][8];   // 32 KB  [k][r]
    __shared__ float wpart[4][8];

    // Cross-h reduction array aliases sA (dead after mainloop): 12 KB needed.
    float* redf = &sA[0][0];

    // ---- prologue: stage the whole A slice ----
    {
        const int r  = t & 7;        // row
        const int kb = t >> 3;       // 0..63, k block of 16
        const float* arow = Am + (size_t)(bm + r) * 1024 + kb * 16;
        float4 v0 = *(const float4*)&arow[0];
        float4 v1 = *(const float4*)&arow[4];
        float4 v2 = *(const float4*)&arow[8];
        float4 v3 = *(const float4*)&arow[12];
        const int k0 = kb * 16;
        sA[k0 +  0][r] = v0.x; sA[k0 +  1][r] = v0.y; sA[k0 +  2][r] = v0.z; sA[k0 +  3][r] = v0.w;
        sA[k0 +  4][r] = v1.x; sA[k0 +  5][r] = v1.y; sA[k0 +  6][r] = v1.z; sA[k0 +  7][r] = v1.w;
        sA[k0 +  8][r] = v2.x; sA[k0 +  9][r] = v2.y; sA[k0 + 10][r] = v2.z; sA[k0 + 11][r] = v2.w;
        sA[k0 + 12][r] = v3.x; sA[k0 + 13][r] = v3.y; sA[k0 + 14][r] = v3.z; sA[k0 + 15][r] = v3.w;
    }
    __syncthreads();

    float acc[8] = {0.f, 0.f, 0.f, 0.f, 0.f, 0.f, 0.f, 0.f};

    // Column stream pointer: g for chunk ch, elem kk = Xcol[(ch*8+kk)*128]
    const float* Xcol = X + (size_t)(h * 256) * DIM + c;

    float ga[8], gb[8];
    #pragma unroll
    for (int kk = 0; kk < 8; kk++) ga[kk] = Xcol[kk * DIM];

    const int kq = h * 256;   // quarter base into sA

    // ---- barrier-free mainloop: 32 chunks of 8 k, ping-pong g registers ----
    #pragma unroll 1
    for (int ch = 0; ch < 32; ch += 2) {
        // prefetch chunk ch+1 into gb
        if (ch + 1 < 32) {
            #pragma unroll
            for (int kk = 0; kk < 8; kk++)
                gb[kk] = Xcol[((ch + 1) * 8 + kk) * DIM];
        }
        // compute chunk ch from ga
        #pragma unroll
        for (int kk = 0; kk < 8; kk++) {
            const int k = kq + ch * 8 + kk;
            const float4 a03 = *(const float4*)&sA[k][0];
            const float4 a47 = *(const float4*)&sA[k][4];
            const float g = ga[kk];
            acc[0] = fmaf(a03.x, g, acc[0]);
            acc[1] = fmaf(a03.y, g, acc[1]);
            acc[2] = fmaf(a03.z, g, acc[2]);
            acc[3] = fmaf(a03.w, g, acc[3]);
            acc[4] = fmaf(a47.x, g, acc[4]);
            acc[5] = fmaf(a47.y, g, acc[5]);
            acc[6] = fmaf(a47.z, g, acc[6]);
            acc[7] = fmaf(a47.w, g, acc[7]);
        }
        // prefetch chunk ch+2 into ga
        if (ch + 2 < 32) {
            #pragma unroll
            for (int kk = 0; kk < 8; kk++)
                ga[kk] = Xcol[((ch + 2) * 8 + kk) * DIM];
        }
        // compute chunk ch+1 from gb
        #pragma unroll
        for (int kk = 0; kk < 8; kk++) {
            const int k = kq + (ch + 1) * 8 + kk;
            const float4 a03 = *(const float4*)&sA[k][0];
            const float4 a47 = *(const float4*)&sA[k][4];
            const float g = gb[kk];
            acc[0] = fmaf(a03.x, g, acc[0]);
            acc[1] = fmaf(a03.y, g, acc[1]);
            acc[2] = fmaf(a03.z, g, acc[2]);
            acc[3] = fmaf(a03.w, g, acc[3]);
            acc[4] = fmaf(a47.x, g, acc[4]);
            acc[5] = fmaf(a47.y, g, acc[5]);
            acc[6] = fmaf(a47.z, g, acc[6]);
            acc[7] = fmaf(a47.w, g, acc[7]);
        }
    }

    // ---- cross-h reduction (redf aliases sA; all sA reads are done after
    //      the barrier below) ----
    __syncthreads();
    if (h > 0) {
        #pragma unroll
        for (int j = 0; j < 8; j++) redf[((h - 1) * 128 + c) * 8 + j] = acc[j];
    }
    __syncthreads();

    float sv[8];
    if (h == 0) {
        #pragma unroll
        for (int hh = 0; hh < 3; hh++)
            #pragma unroll
            for (int j = 0; j < 8; j++) acc[j] += redf[(hh * 128 + c) * 8 + j];

        if (!EPI) {
            #pragma unroll
            for (int j = 0; j < 8; j++) Y[(bm + j) * DIM + c] = acc[j];
        } else {
            const float SELU_SCALE = 1.0507009873554804934f;
            const float SELU_ALPHA = 1.6732632423543772848f;
            float sq[8];
            #pragma unroll
            for (int j = 0; j < 8; j++) {
                sv[j] = (acc[j] > 0.f) ? SELU_SCALE * acc[j]
                                       : SELU_SCALE * SELU_ALPHA * (expf(acc[j]) - 1.f);
                sq[j] = sv[j] * sv[j];
            }
            #pragma unroll
            for (int j = 0; j < 8; j++)
                #pragma unroll
                for (int o = 16; o; o >>= 1)
                    sq[j] += __shfl_xor_sync(0xFFFFFFFFu, sq[j], o);
            if ((c & 31) == 0) {
                #pragma unroll
                for (int j = 0; j < 8; j++) wpart[c >> 5][j] = sq[j];
            }
        }
    }

    if (EPI) {
        __syncthreads();
        if (h == 0) {
            #pragma unroll
            for (int j = 0; j < 8; j++) {
                const float inv = rsqrtf(wpart[0][j] + wpart[1][j] + wpart[2][j] + wpart[3][j]);
                Y[(bm + j) * DIM + c] = sv[j] * inv;
            }
        }
    }
}

// ---------------------------------------------------------------------------
// Launch: gather -> ag = A@g -> out = norm(selu(D@ag))
// (attention/entmax path is analytically identity on g: scores constant
//  along L, entmax of a constant is uniform, sum(p)*g = g)
// ---------------------------------------------------------------------------
extern "C" void kernel_launch(void* const* d_in, const int* in_sizes, int n_in,
                              void* d_out, int out_size)
{
    const float* emb   = (const float*)d_in[0];  // [500000, 128]
    const void*  items = d_in[1];                // [1024, 200] int64/int32
    const float* Amat  = (const float*)d_in[2];  // [1024, 1024]
    const float* Dmat  = (const float*)d_in[3];  // [1024, 1024]
    float* out = (float*)d_out;                  // [1024, 128]

    float* g;  cudaGetSymbolAddress((void**)&g,  g_buf);
    float* ag; cudaGetSymbolAddress((void**)&ag, ag_buf);

    gather_sum_kernel<<<BATCH, 256>>>(emb, items);

    gemm_1024x128_kernel<false><<<BATCH / 8, 512>>>(Amat, g, ag);   // ag = A@g
    gemm_1024x128_kernel<true ><<<BATCH / 8, 512>>>(Dmat, ag, out); // out = norm(selu(D@ag))
}

// round 9
// speedup vs baseline: 2.3816x; 1.0231x over previous
#include <cuda_runtime.h>
#include <cstdint>

#define BATCH 1024
#define SEQL  200
#define DIM   128

// Scratch (allocation-free rule: __device__ globals)
__device__ float g_buf[BATCH * DIM];
__device__ float ag_buf[BATCH * DIM];

// Packed fp32x2 FMA (Blackwell FFMA2 — only reachable via PTX fma.rn.f32x2)
__device__ __forceinline__ void ffma2(unsigned long long& d,
                                      unsigned long long a,
                                      unsigned long long b) {
    asm("fma.rn.f32x2 %0, %1, %2, %0;" : "+l"(d) : "l"(a), "l"(b));
}
__device__ __forceinline__ float2 unpack2(unsigned long long v) {
    float2 f;
    asm("mov.b64 {%0, %1}, %2;" : "=f"(f.x), "=f"(f.y) : "l"(v));
    return f;
}
__device__ __forceinline__ unsigned long long dup2(float g) {
    unsigned long long r;
    asm("mov.b64 %0, {%1, %1};" : "=l"(r) : "f"(g));
    return r;
}

// ---------------------------------------------------------------------------
// Kernel 1: g[b] = sum_l item_embedding[items[b,l]]
// DRAM-saturated for random 512B rows (~3.9-4.0 TB/s ~= compulsory traffic
// ceiling); structure unchanged.
// ---------------------------------------------------------------------------
__global__ void __launch_bounds__(256) gather_sum_kernel(
    const float* __restrict__ emb,
    const void* __restrict__ items_raw)
{
    const int b    = blockIdx.x;
    const int t    = threadIdx.x;
    const int w    = t >> 5;
    const int lane = t & 31;

    __shared__ int sidx[SEQL];
    __shared__ int mode64;
    __shared__ float4 spart[8][32];

    if (t == 0) {
        // int64 storage => odd int32 words of first 16 elements are all zero
        const int* p = (const int*)items_raw;
        int ok = 1;
        #pragma unroll
        for (int i = 0; i < 16; i++) ok &= (p[2 * i + 1] == 0);
        mode64 = ok;
    }
    __syncthreads();

    if (t < SEQL) {
        if (mode64) sidx[t] = (int)((const long long*)items_raw)[(long long)b * SEQL + t];
        else        sidx[t] = ((const int*)items_raw)[b * SEQL + t];
    }
    __syncthreads();

    float4 acc[5], v[5];
    #pragma unroll
    for (int j = 0; j < 5; j++) acc[j] = make_float4(0.f, 0.f, 0.f, 0.f);

    #pragma unroll
    for (int j = 0; j < 5; j++)
        v[j] = *(const float4*)&emb[(size_t)sidx[w + 8 * j] * DIM + lane * 4];

    #pragma unroll
    for (int s = 0; s < 5; s++) {
        float4 nv[5];
        if (s < 4) {
            #pragma unroll
            for (int j = 0; j < 5; j++)
                nv[j] = *(const float4*)&emb[(size_t)sidx[w + 8 * (5 * (s + 1) + j)] * DIM + lane * 4];
        }
        #pragma unroll
        for (int j = 0; j < 5; j++) {
            acc[j].x += v[j].x; acc[j].y += v[j].y;
            acc[j].z += v[j].z; acc[j].w += v[j].w;
        }
        if (s < 4) {
            #pragma unroll
            for (int j = 0; j < 5; j++) v[j] = nv[j];
        }
    }

    float4 s4;
    s4.x = ((acc[0].x + acc[1].x) + (acc[2].x + acc[3].x)) + acc[4].x;
    s4.y = ((acc[0].y + acc[1].y) + (acc[2].y + acc[3].y)) + acc[4].y;
    s4.z = ((acc[0].z + acc[1].z) + (acc[2].z + acc[3].z)) + acc[4].z;
    s4.w = ((acc[0].w + acc[1].w) + (acc[2].w + acc[3].w)) + acc[4].w;

    spart[w][lane] = s4;
    __syncthreads();
    if (w < 4) {
        float4 a = spart[w][lane], c = spart[w + 4][lane];
        a.x += c.x; a.y += c.y; a.z += c.z; a.w += c.w;
        spart[w][lane] = a;
    }
    __syncthreads();
    if (w < 2) {
        float4 a = spart[w][lane], c = spart[w + 2][lane];
        a.x += c.x; a.y += c.y; a.z += c.z; a.w += c.w;
        spart[w][lane] = a;
    }
    __syncthreads();
    if (w == 0) {
        float4 a = spart[0][lane], c = spart[1][lane];
        a.x += c.x; a.y += c.y; a.z += c.z; a.w += c.w;
        *(float4*)&g_buf[b * DIM + lane * 4] = a;
    }
}

// ---------------------------------------------------------------------------
// Kernel 2: Y[1024,128] = Am[1024,1024] @ X[1024,128]  (+fused selu/norm)
//
// Barrier-free mainloop (round-8 structure) + packed FFMA2 math:
//  - A slice (8 x 1024 = 32 KB) staged once; sA[k][8] row-pairs are already
//    contiguous -> double2 LDS.128 yields packed pairs (a0,a1),(a2,a3).
//  - acc[j] = packed f32x2 partial for rows (2j, 2j+1).
//  - Per kk: 2 LDS.128 + 1 mov.b64 dup + 4 FFMA2 = 7 issue slots in the
//    8-cyc FFMA2 window -> fma-pipe floor halves vs scalar FFMA.
//  - g streams through registers from L2 (no smem, no barriers).
// ---------------------------------------------------------------------------
template <bool EPI>
__global__ void __launch_bounds__(512) gemm_1024x128_kernel(
    const float* __restrict__ Am,
    const float* __restrict__ X,
    float* __restrict__ Y)
{
    const int t  = threadIdx.x;
    const int bm = blockIdx.x * 8;
    const int c  = t & 127;     // column
    const int h  = t >> 7;      // K quarter 0..3

    __shared__ __align__(16) float sA[1024][8];   // 32 KB  [k][r]
    __shared__ float wpart[4][8];

    // Cross-h reduction array aliases sA (dead after mainloop): 12 KB needed.
    float* redf = &sA[0][0];

    // ---- prologue: stage the whole A slice ----
    {
        const int r  = t & 7;        // row
        const int kb = t >> 3;       // 0..63, k block of 16
        const float* arow = Am + (size_t)(bm + r) * 1024 + kb * 16;
        float4 v0 = *(const float4*)&arow[0];
        float4 v1 = *(const float4*)&arow[4];
        float4 v2 = *(const float4*)&arow[8];
        float4 v3 = *(const float4*)&arow[12];
        const int k0 = kb * 16;
        sA[k0 +  0][r] = v0.x; sA[k0 +  1][r] = v0.y; sA[k0 +  2][r] = v0.z; sA[k0 +  3][r] = v0.w;
        sA[k0 +  4][r] = v1.x; sA[k0 +  5][r] = v1.y; sA[k0 +  6][r] = v1.z; sA[k0 +  7][r] = v1.w;
        sA[k0 +  8][r] = v2.x; sA[k0 +  9][r] = v2.y; sA[k0 + 10][r] = v2.z; sA[k0 + 11][r] = v2.w;
        sA[k0 + 12][r] = v3.x; sA[k0 + 13][r] = v3.y; sA[k0 + 14][r] = v3.z; sA[k0 + 15][r] = v3.w;
    }
    __syncthreads();

    // acc[j] = packed (row 2j, row 2j+1) partials
    unsigned long long acc[4] = {0ull, 0ull, 0ull, 0ull};

    const float* Xcol = X + (size_t)(h * 256) * DIM + c;

    float ga[8], gb[8];
    #pragma unroll
    for (int kk = 0; kk < 8; kk++) ga[kk] = Xcol[kk * DIM];

    const int kq = h * 256;   // quarter base into sA

    // ---- barrier-free mainloop: 32 chunks of 8 k, ping-pong g registers ----
    #pragma unroll 1
    for (int ch = 0; ch < 32; ch += 2) {
        if (ch + 1 < 32) {
            #pragma unroll
            for (int kk = 0; kk < 8; kk++)
                gb[kk] = Xcol[((ch + 1) * 8 + kk) * DIM];
        }
        #pragma unroll
        for (int kk = 0; kk < 8; kk++) {
            const int k = kq + ch * 8 + kk;
            const double2 p01 = *(const double2*)&sA[k][0];
            const double2 p23 = *(const double2*)&sA[k][4];
            const unsigned long long gd = dup2(ga[kk]);
            ffma2(acc[0], __double_as_longlong(p01.x), gd);
            ffma2(acc[1], __double_as_longlong(p01.y), gd);
            ffma2(acc[2], __double_as_longlong(p23.x), gd);
            ffma2(acc[3], __double_as_longlong(p23.y), gd);
        }
        if (ch + 2 < 32) {
            #pragma unroll
            for (int kk = 0; kk < 8; kk++)
                ga[kk] = Xcol[((ch + 2) * 8 + kk) * DIM];
        }
        #pragma unroll
        for (int kk = 0; kk < 8; kk++) {
            const int k = kq + (ch + 1) * 8 + kk;
            const double2 p01 = *(const double2*)&sA[k][0];
            const double2 p23 = *(const double2*)&sA[k][4];
            const unsigned long long gd = dup2(gb[kk]);
            ffma2(acc[0], __double_as_longlong(p01.x), gd);
            ffma2(acc[1], __double_as_longlong(p01.y), gd);
            ffma2(acc[2], __double_as_longlong(p23.x), gd);
            ffma2(acc[3], __double_as_longlong(p23.y), gd);
        }
    }

    // unpack packed accs to 8 scalars
    float s[8];
    #pragma unroll
    for (int j = 0; j < 4; j++) {
        const float2 f = unpack2(acc[j]);
        s[2 * j] = f.x; s[2 * j + 1] = f.y;
    }

    // ---- cross-h reduction (redf aliases sA) ----
    __syncthreads();
    if (h > 0) {
        #pragma unroll
        for (int j = 0; j < 8; j++) redf[((h - 1) * 128 + c) * 8 + j] = s[j];
    }
    __syncthreads();

    float sv[8];
    if (h == 0) {
        #pragma unroll
        for (int hh = 0; hh < 3; hh++)
            #pragma unroll
            for (int j = 0; j < 8; j++) s[j] += redf[(hh * 128 + c) * 8 + j];

        if (!EPI) {
            #pragma unroll
            for (int j = 0; j < 8; j++) Y[(bm + j) * DIM + c] = s[j];
        } else {
            const float SELU_SCALE = 1.0507009873554804934f;
            const float SELU_ALPHA = 1.6732632423543772848f;
            float sq[8];
            #pragma unroll
            for (int j = 0; j < 8; j++) {
                sv[j] = (s[j] > 0.f) ? SELU_SCALE * s[j]
                                     : SELU_SCALE * SELU_ALPHA * (expf(s[j]) - 1.f);
                sq[j] = sv[j] * sv[j];
            }
            #pragma unroll
            for (int j = 0; j < 8; j++)
                #pragma unroll
                for (int o = 16; o; o >>= 1)
                    sq[j] += __shfl_xor_sync(0xFFFFFFFFu, sq[j], o);
            if ((c & 31) == 0) {
                #pragma unroll
                for (int j = 0; j < 8; j++) wpart[c >> 5][j] = sq[j];
            }
        }
    }

    if (EPI) {
        __syncthreads();
        if (h == 0) {
            #pragma unroll
            for (int j = 0; j < 8; j++) {
                const float inv = rsqrtf(wpart[0][j] + wpart[1][j] + wpart[2][j] + wpart[3][j]);
                Y[(bm + j) * DIM + c] = sv[j] * inv;
            }
        }
    }
}

// ---------------------------------------------------------------------------
// Launch: gather -> ag = A@g -> out = norm(selu(D@ag))
// (attention/entmax path is analytically identity on g: scores constant
//  along L, entmax of a constant is uniform, sum(p)*g = g)
// ---------------------------------------------------------------------------
extern "C" void kernel_launch(void* const* d_in, const int* in_sizes, int n_in,
                              void* d_out, int out_size)
{
    const float* emb   = (const float*)d_in[0];  // [500000, 128]
    const void*  items = d_in[1];                // [1024, 200] int64/int32
    const float* Amat  = (const float*)d_in[2];  // [1024, 1024]
    const float* Dmat  = (const float*)d_in[3];  // [1024, 1024]
    float* out = (float*)d_out;                  // [1024, 128]

    float* g;  cudaGetSymbolAddress((void**)&g,  g_buf);
    float* ag; cudaGetSymbolAddress((void**)&ag, ag_buf);

    gather_sum_kernel<<<BATCH, 256>>>(emb, items);

    gemm_1024x128_kernel<false><<<BATCH / 8, 512>>>(Amat, g, ag);   // ag = A@g
    gemm_1024x128_kernel<true ><<<BATCH / 8, 512>>>(Dmat, ag, out); // out = norm(selu(D@ag))
}